// round 16
// baseline (speedup 1.0000x reference)
#include <cuda_runtime.h>
#include <cuda_bf16.h>
#include <cuda_fp16.h>

#define Bc 2
#define Sc 2048
#define Dc 1024
#define Hc 16
#define Mc (Bc*Sc)

typedef unsigned u32;
typedef __nv_bfloat16 bf16;

// ---------------- scratch ----------------
__device__ bf16 g_xh[(size_t)Mc*Dc], g_xl[(size_t)Mc*Dc];
__device__ bf16 g_wh[4*Dc*Dc], g_wl[4*Dc*Dc];
__device__ bf16 g_qh[(size_t)Mc*Dc], g_ql[(size_t)Mc*Dc];
__device__ bf16 g_kh[(size_t)Mc*Dc], g_kl[(size_t)Mc*Dc];
__device__ __half g_vth[(size_t)Bc*Dc*Sc], g_vtl[(size_t)Bc*Dc*Sc];
__device__ bf16 g_aoh[(size_t)Mc*Dc], g_aol[(size_t)Mc*Dc];
__device__ float g_v[(size_t)Mc*Dc];
__device__ __half g_wraw[(size_t)Mc*Hc*Sc];   // w' fp16, frag-native
__device__ float g_mu[(size_t)4096*1024];      // per (wg, tile, sub, row) m_used

// ---------------- helpers ----------------
__device__ __forceinline__ void mma16816(float* c, const u32* a, const u32* b) {
    asm volatile("mma.sync.aligned.m16n8k16.row.col.f32.bf16.bf16.f32 "
        "{%0,%1,%2,%3},{%4,%5,%6,%7},{%8,%9},{%0,%1,%2,%3};"
        : "+f"(c[0]), "+f"(c[1]), "+f"(c[2]), "+f"(c[3])
        : "r"(a[0]), "r"(a[1]), "r"(a[2]), "r"(a[3]), "r"(b[0]), "r"(b[1]));
}
__device__ __forceinline__ void mma16816h(float* c, const u32* a, const u32* b) {
    asm volatile("mma.sync.aligned.m16n8k16.row.col.f32.f16.f16.f32 "
        "{%0,%1,%2,%3},{%4,%5,%6,%7},{%8,%9},{%0,%1,%2,%3};"
        : "+f"(c[0]), "+f"(c[1]), "+f"(c[2]), "+f"(c[3])
        : "r"(a[0]), "r"(a[1]), "r"(a[2]), "r"(a[3]), "r"(b[0]), "r"(b[1]));
}
__device__ __forceinline__ void ldsm4(u32* r, u32 a) {
    asm volatile("ldmatrix.sync.aligned.m8n8.x4.shared.b16 {%0,%1,%2,%3}, [%4];"
        : "=r"(r[0]), "=r"(r[1]), "=r"(r[2]), "=r"(r[3]) : "r"(a));
}
__device__ __forceinline__ u32 smem_u32(const void* p) {
    return (u32)__cvta_generic_to_shared(p);
}
__device__ __forceinline__ u32 pkbf(float x, float y) {
    bf16 a = __float2bfloat16(x), b = __float2bfloat16(y);
    return (u32)__bfloat16_as_ushort(a) | ((u32)__bfloat16_as_ushort(b) << 16);
}
__device__ __forceinline__ float bflo(float x) {
    return x - __bfloat162float(__float2bfloat16(x));
}
__device__ __forceinline__ void cpa16(void* s, const void* g) {
    u32 ss = (u32)__cvta_generic_to_shared(s);
    asm volatile("cp.async.ca.shared.global [%0], [%1], 16;" :: "r"(ss), "l"(g));
}
__device__ __forceinline__ void cpcommit() { asm volatile("cp.async.commit_group;"); }
template<int N> __device__ __forceinline__ void cpwait() { asm volatile("cp.async.wait_group %0;" :: "n"(N)); }

// FMA-pipe exp (x <= 0), rel err ~4e-5
__device__ __forceinline__ float fexp(float x) {
    float y = fmaf(x, 1.4426950408889634f, 12582912.0f);
    float n = y - 12582912.0f;
    float f = fmaf(x, 1.4426950408889634f, -n);
    float p = 0.00961812910f;
    p = fmaf(p, f, 0.05550410866f);
    p = fmaf(p, f, 0.24022650696f);
    p = fmaf(p, f, 0.69314718056f);
    p = fmaf(p, f, 1.0f);
    return __int_as_float(__float_as_int(p) + (__float_as_int(y) << 23));
}

// ---------------- merged conversions: x + 4 weights in one launch ----------------
__global__ __launch_bounds__(256) void cvt_all(const float* __restrict__ x,
                                               const float* __restrict__ w0,
                                               const float* __restrict__ w1,
                                               const float* __restrict__ w2,
                                               const float* __restrict__ w3) {
    int bi = blockIdx.x;
    const float* in;
    bf16 *oh, *ol;
    size_t i;
    if (bi < 4096) {
        in = x; oh = g_xh; ol = g_xl;
        i = (size_t)bi * 256 + threadIdx.x;
    } else {
        int wi = (bi - 4096) >> 10;
        in = wi == 0 ? w0 : wi == 1 ? w1 : wi == 2 ? w2 : w3;
        oh = g_wh + (size_t)wi * Dc * Dc;
        ol = g_wl + (size_t)wi * Dc * Dc;
        i = (size_t)((bi - 4096) & 1023) * 256 + threadIdx.x;
    }
    float4 v = ((const float4*)in)[i];
    ((uint2*)oh)[i] = make_uint2(pkbf(v.x, v.y), pkbf(v.z, v.w));
    ((uint2*)ol)[i] = make_uint2(pkbf(bflo(v.x), bflo(v.y)), pkbf(bflo(v.z), bflo(v.w)));
}

__global__ __launch_bounds__(256) void vtrans() {
    __shared__ float ts[32][33];
    int tx = threadIdx.x & 31, ty = threadIdx.x >> 5;
    int s0 = blockIdx.x * 32, d0 = blockIdx.y * 32, b = blockIdx.z;
#pragma unroll
    for (int i = 0; i < 4; i++)
        ts[ty + i * 8][tx] = g_v[((size_t)(b * Sc + s0 + ty + i * 8)) * Dc + d0 + tx];
    __syncthreads();
#pragma unroll
    for (int i = 0; i < 4; i++) {
        int d = ty + i * 8;
        float v = ts[tx][d];
        size_t o = ((size_t)(b * Dc + d0 + d)) * Sc + s0 + tx;
        __half vh = __float2half(v);
        g_vth[o] = vh;
        g_vtl[o] = __float2half(v - __half2float(vh));
    }
}

// ============ QKV merged / out-proj 3-term bf16 GEMM ============
__global__ __launch_bounds__(256, 2) void gemm_bf3(
    const bf16* __restrict__ Ah0, const bf16* __restrict__ Al0,
    float* __restrict__ Cf,
    const float* __restrict__ cosb, const float* __restrict__ sinb, int qkv) {
    __shared__ bf16 Ahs[2][128][24], Als[2][128][24], Bhs[2][128][24], Bls[2][128][24];
    int t = threadIdx.x, lane = t & 31, w = t >> 5;
    int wm = w & 1, wn = w >> 1;
    int g = lane >> 2, c2 = (lane & 3) * 2;
    int which = qkv ? (blockIdx.x >> 3) : 3;
    int bcol = (blockIdx.x & 7) * 128;
    int brow = blockIdx.y * 128;
    const bf16* Ah = Ah0;
    const bf16* Al = Al0;
    const bf16* Bh = g_wh + (size_t)which * Dc * Dc;
    const bf16* Bl = g_wl + (size_t)which * Dc * Dc;

    float acc[4][4][4];
#pragma unroll
    for (int a = 0; a < 4; a++)
#pragma unroll
        for (int b2 = 0; b2 < 4; b2++)
#pragma unroll
            for (int q = 0; q < 4; q++) acc[a][b2][q] = 0.f;

    int arow = wm * 64 + ((lane >> 3) & 1) * 8 + (lane & 7);
    int acol = ((lane >> 4) & 1) * 8;
    int brw  = wn * 32 + ((lane >> 4) & 1) * 8 + (lane & 7);
    int bcl  = ((lane >> 3) & 1) * 8;

    int lr = t >> 1, lc = (t & 1) * 8;
    const bf16* pah = Ah + (size_t)(brow + lr) * Dc + lc;
    const bf16* pal = Al + (size_t)(brow + lr) * Dc + lc;
    const bf16* pbh = Bh + (size_t)(bcol + lr) * Dc + lc;
    const bf16* pbl = Bl + (size_t)(bcol + lr) * Dc + lc;

#define GLOAD(st, k0) { \
        cpa16(&Ahs[st][lr][lc], pah + (k0)); cpa16(&Als[st][lr][lc], pal + (k0)); \
        cpa16(&Bhs[st][lr][lc], pbh + (k0)); cpa16(&Bls[st][lr][lc], pbl + (k0)); }

    GLOAD(0, 0); cpcommit();
    for (int kt = 0; kt < 64; kt++) {
        cpwait<0>();
        __syncthreads();
        if (kt < 63) { GLOAD((kt + 1) & 1, (kt + 1) * 16); cpcommit(); }
        int st = kt & 1;
        u32 aBH = smem_u32(&Ahs[st][arow][acol]);
        u32 aBL = smem_u32(&Als[st][arow][acol]);
        u32 bBH = smem_u32(&Bhs[st][brw][bcl]);
        u32 bBL = smem_u32(&Bls[st][brw][bcl]);
        u32 a_h[4][4], a_l[4][4], b_h[2][4], b_l[2][4];
#pragma unroll
        for (int mf = 0; mf < 4; mf++) {
            ldsm4(a_h[mf], aBH + mf * 768);
            ldsm4(a_l[mf], aBL + mf * 768);
        }
#pragma unroll
        for (int nfp = 0; nfp < 2; nfp++) {
            ldsm4(b_h[nfp], bBH + nfp * 768);
            ldsm4(b_l[nfp], bBL + nfp * 768);
        }
#pragma unroll
        for (int nf = 0; nf < 4; nf++) {
            const u32* bh2 = &b_h[nf >> 1][(nf & 1) * 2];
            const u32* bl2 = &b_l[nf >> 1][(nf & 1) * 2];
#pragma unroll
            for (int mf = 0; mf < 4; mf++) {
                mma16816(acc[mf][nf], a_h[mf], bh2);
                mma16816(acc[mf][nf], a_h[mf], bl2);
                mma16816(acc[mf][nf], a_l[mf], bh2);
            }
        }
    }
#undef GLOAD
    if (which >= 2) {
        float* dst = (which == 2) ? g_v : Cf;
#pragma unroll
        for (int mf = 0; mf < 4; mf++)
#pragma unroll
            for (int nf = 0; nf < 4; nf++) {
                int r = brow + wm * 64 + mf * 16 + g;
                int c = bcol + wn * 32 + nf * 8 + c2;
                *(float2*)&dst[(size_t)r * Dc + c]       = make_float2(acc[mf][nf][0], acc[mf][nf][1]);
                *(float2*)&dst[(size_t)(r + 8) * Dc + c] = make_float2(acc[mf][nf][2], acc[mf][nf][3]);
            }
    } else {
        bf16* Ch = which == 0 ? g_qh : g_kh;
        bf16* Cl = which == 0 ? g_ql : g_kl;
#pragma unroll
        for (int mf = 0; mf < 4; mf++)
#pragma unroll
            for (int nf = 0; nf < 4; nf++) {
                int r = brow + wm * 64 + mf * 16 + g;
                int c = bcol + wn * 32 + nf * 8 + c2;
                int pi = (c & 63) >> 1;
                int sA = r & 2047, sB = (r + 8) & 2047;
                float csA = cosb[sA * 32 + pi], snA = sinb[sA * 32 + pi];
                float csB = cosb[sB * 32 + pi], snB = sinb[sB * 32 + pi];
                float a0 = acc[mf][nf][0], a1 = acc[mf][nf][1];
                float a2 = acc[mf][nf][2], a3 = acc[mf][nf][3];
                float o0 = a0 * csA - a1 * snA, o1 = a0 * snA + a1 * csA;
                float o2 = a2 * csB - a3 * snB, o3 = a2 * snB + a3 * csB;
                size_t off = (size_t)r * Dc + c;
                *(u32*)(Ch + off) = pkbf(o0, o1);
                *(u32*)(Cl + off) = pkbf(bflo(o0), bflo(o1));
                off = (size_t)(r + 8) * Dc + c;
                *(u32*)(Ch + off) = pkbf(o2, o3);
                *(u32*)(Cl + off) = pkbf(bflo(o2), bflo(o3));
            }
    }
}

// ---------------- fused pass 1 (flash) + renorm epilogue ----------------
#define ATTN1_SMEM 73728
__global__ __launch_bounds__(256, 2) void attn1(float* __restrict__ ent, float* __restrict__ attnw) {
    extern __shared__ char sm[];
    bf16*   KH = (bf16*)sm;
    bf16*   KL = (bf16*)(sm + 18432);
    __half* VH = (__half*)(sm + 36864);
    __half* VL = (__half*)(sm + 55296);
#define KHS(st,r,c) (KH + (st)*4608 + (r)*72 + (c))
#define KLS(st,r,c) (KL + (st)*4608 + (r)*72 + (c))
#define VHS(st,r,c) (VH + (st)*4608 + (r)*72 + (c))
#define VLS(st,r,c) (VL + (st)*4608 + (r)*72 + (c))
    int t = threadIdx.x, lane = t & 31, w = t >> 5;
    int g = lane >> 2, c2 = (lane & 3) * 2;
    int b = blockIdx.y >> 4, h = blockIdx.y & 15;
    int i0 = blockIdx.x * 128 + w * 16;

    const bf16* qh = g_qh + ((size_t)(b * Sc + i0 + g)) * Dc + h * 64;
    const bf16* ql = g_ql + ((size_t)(b * Sc + i0 + g)) * Dc + h * 64;
    u32 ah[4][4], al[4][4];
#pragma unroll
    for (int kf = 0; kf < 4; kf++) {
        ah[kf][0] = *(const u32*)(qh + kf * 16 + c2);
        ah[kf][1] = *(const u32*)(qh + 8 * Dc + kf * 16 + c2);
        ah[kf][2] = *(const u32*)(qh + kf * 16 + c2 + 8);
        ah[kf][3] = *(const u32*)(qh + 8 * Dc + kf * 16 + c2 + 8);
        al[kf][0] = *(const u32*)(ql + kf * 16 + c2);
        al[kf][1] = *(const u32*)(ql + 8 * Dc + kf * 16 + c2);
        al[kf][2] = *(const u32*)(ql + kf * 16 + c2 + 8);
        al[kf][3] = *(const u32*)(ql + 8 * Dc + kf * 16 + c2 + 8);
    }

    int kr = t >> 2, kc = (t & 3) * 16;
    const bf16* kgh = g_kh + ((size_t)(b * Sc + kr)) * Dc + h * 64 + kc;
    const bf16* kgl = g_kl + ((size_t)(b * Sc + kr)) * Dc + h * 64 + kc;
    const __half* vgh = g_vth + ((size_t)(b * Dc + h * 64 + kr)) * Sc + kc;
    const __half* vgl = g_vtl + ((size_t)(b * Dc + h * 64 + kr)) * Sc + kc;

#define TLOAD(st, j0) { \
        cpa16(KHS(st,kr,kc),     kgh + (size_t)(j0) * Dc); \
        cpa16(KHS(st,kr,kc+8),   kgh + (size_t)(j0) * Dc + 8); \
        cpa16(KLS(st,kr,kc),     kgl + (size_t)(j0) * Dc); \
        cpa16(KLS(st,kr,kc+8),   kgl + (size_t)(j0) * Dc + 8); \
        cpa16(VHS(st,kr,kc),     vgh + (j0)); \
        cpa16(VHS(st,kr,kc+8),   vgh + (j0) + 8); \
        cpa16(VLS(st,kr,kc),     vgl + (j0)); \
        cpa16(VLS(st,kr,kc+8),   vgl + (j0) + 8); }

    int brow = ((lane >> 4) & 1) * 8 + (lane & 7);
    int bcol = ((lane >> 3) & 1) * 8;

    float m0 = -1e30f, m1 = -1e30f, l0 = 0.f, l1 = 0.f, ws0 = 0.f, ws1 = 0.f;
    float o[8][4];
#pragma unroll
    for (int n = 0; n < 8; n++)
#pragma unroll
        for (int q = 0; q < 4; q++) o[n][q] = 0.f;

    size_t wg = ((size_t)blockIdx.y * 16 + blockIdx.x) * 8 + w;
    uint2* wout = (uint2*)g_wraw + wg * 8192;
    float* muout = g_mu + wg * 1024;

    TLOAD(0, 0); cpcommit();
    for (int jt = 0; jt < 32; jt++) {
        int j0 = jt * 64;
        cpwait<0>();
        __syncthreads();
        if (jt < 31) { TLOAD((jt + 1) & 1, j0 + 64); cpcommit(); }
        int st = jt & 1;
        u32 kBH0 = smem_u32(KHS(st, brow, bcol));
        u32 kBL0 = smem_u32(KLS(st, brow, bcol));
        u32 vBH = smem_u32(VHS(st, brow, bcol));
        u32 vBL = smem_u32(VLS(st, brow, bcol));
#pragma unroll
        for (int sub = 0; sub < 2; sub++) {
            u32 kBH = kBH0 + sub * 32 * 144;
            u32 kBL = kBL0 + sub * 32 * 144;
            float sc[4][4];
#pragma unroll
            for (int nt = 0; nt < 4; nt++) { sc[nt][0] = sc[nt][1] = sc[nt][2] = sc[nt][3] = 0.f; }
#pragma unroll
            for (int ntp = 0; ntp < 2; ntp++) {
#pragma unroll
                for (int kf = 0; kf < 4; kf++) {
                    u32 off = (u32)(ntp * 16 * 144 + kf * 32);
                    u32 bh4[4], bl4[4];
                    ldsm4(bh4, kBH + off);
                    ldsm4(bl4, kBL + off);
                    mma16816(sc[2 * ntp],     ah[kf], &bh4[0]);
                    mma16816(sc[2 * ntp],     ah[kf], &bl4[0]);
                    mma16816(sc[2 * ntp],     al[kf], &bh4[0]);
                    mma16816(sc[2 * ntp + 1], ah[kf], &bh4[2]);
                    mma16816(sc[2 * ntp + 1], ah[kf], &bl4[2]);
                    mma16816(sc[2 * ntp + 1], al[kf], &bh4[2]);
                }
            }
#pragma unroll
            for (int nt = 0; nt < 4; nt++) {
                sc[nt][0] *= 0.125f; sc[nt][1] *= 0.125f; sc[nt][2] *= 0.125f; sc[nt][3] *= 0.125f;
            }
            float tm0 = -1e30f, tm1 = -1e30f;
#pragma unroll
            for (int nt = 0; nt < 4; nt++) {
                tm0 = fmaxf(tm0, fmaxf(sc[nt][0], sc[nt][1]));
                tm1 = fmaxf(tm1, fmaxf(sc[nt][2], sc[nt][3]));
            }
            tm0 = fmaxf(tm0, __shfl_xor_sync(~0u, tm0, 1));
            tm0 = fmaxf(tm0, __shfl_xor_sync(~0u, tm0, 2));
            tm1 = fmaxf(tm1, __shfl_xor_sync(~0u, tm1, 1));
            tm1 = fmaxf(tm1, __shfl_xor_sync(~0u, tm1, 2));
            float mn0 = fmaxf(m0, tm0), mn1 = fmaxf(m1, tm1);
            float cr0 = __expf(m0 - mn0), cr1 = __expf(m1 - mn1);
            l0 *= cr0; ws0 *= cr0; l1 *= cr1; ws1 *= cr1;
#pragma unroll
            for (int nt = 0; nt < 4; nt++) {
                float e0 = fexp(sc[nt][0] - mn0), e1 = fexp(sc[nt][1] - mn0);     // FMA pipe
                float e2 = __expf(sc[nt][2] - mn1), e3 = __expf(sc[nt][3] - mn1); // MUFU pipe
                l0 += e0 + e1;
                ws0 = fmaf(e0, sc[nt][0], fmaf(e1, sc[nt][1], ws0));
                l1 += e2 + e3;
                ws1 = fmaf(e2, sc[nt][2], fmaf(e3, sc[nt][3], ws1));
                __half2 p01 = __floats2half2_rn(e0, e1);
                __half2 p23 = __floats2half2_rn(e2, e3);
                u32 u01 = *(u32*)&p01, u23 = *(u32*)&p23;
                wout[(size_t)(j0 / 8 + sub * 4 + nt) * 32 + lane] = make_uint2(u01, u23);
                sc[nt][0] = __uint_as_float(u01);
                sc[nt][1] = __uint_as_float(u23);
            }
            m0 = mn0; m1 = mn1;
            if ((lane & 3) == 0) {
                muout[(jt * 2 + sub) * 16 + g * 2]     = mn0;
                muout[(jt * 2 + sub) * 16 + g * 2 + 1] = mn1;
            }
#pragma unroll
            for (int nt = 0; nt < 8; nt++) {
                o[nt][0] *= cr0; o[nt][1] *= cr0; o[nt][2] *= cr1; o[nt][3] *= cr1;
            }
#pragma unroll
            for (int ntp = 0; ntp < 4; ntp++) {
#pragma unroll
                for (int kf = 0; kf < 2; kf++) {
                    u32 off = (u32)(ntp * 16 * 144 + (sub * 2 + kf) * 32);
                    u32 vh4[4], vl4[4];
                    ldsm4(vh4, vBH + off);
                    ldsm4(vl4, vBL + off);
                    u32 ahg[4] = { __float_as_uint(sc[2 * kf][0]), __float_as_uint(sc[2 * kf][1]),
                                   __float_as_uint(sc[2 * kf + 1][0]), __float_as_uint(sc[2 * kf + 1][1]) };
                    mma16816h(o[2 * ntp],     ahg, &vh4[0]);
                    mma16816h(o[2 * ntp],     ahg, &vl4[0]);
                    mma16816h(o[2 * ntp + 1], ahg, &vh4[2]);
                    mma16816h(o[2 * ntp + 1], ahg, &vl4[2]);
                }
            }
        }
    }
#undef TLOAD
#pragma unroll
    for (int x = 1; x < 4; x <<= 1) {
        float om = __shfl_xor_sync(~0u, m0, x), ol = __shfl_xor_sync(~0u, l0, x),
              ow = __shfl_xor_sync(~0u, ws0, x);
        float mn = fmaxf(m0, om), ca = __expf(m0 - mn), cb = __expf(om - mn);
        l0 = l0 * ca + ol * cb; ws0 = ws0 * ca + ow * cb; m0 = mn;
        om = __shfl_xor_sync(~0u, m1, x); ol = __shfl_xor_sync(~0u, l1, x);
        ow = __shfl_xor_sync(~0u, ws1, x);
        mn = fmaxf(m1, om); ca = __expf(m1 - mn); cb = __expf(om - mn);
        l1 = l1 * ca + ol * cb; ws1 = ws1 * ca + ow * cb; m1 = mn;
    }
    float li0 = 1.f / l0, li1 = 1.f / l1;
    if ((lane & 3) == 0) {
        int idx0 = (b * Sc + i0 + g) * Hc + h;
        ent[idx0]          = __log2f(l0) + (m0 - ws0 / l0) * 1.4426950408889634f;
        ent[idx0 + 8 * Hc] = __log2f(l1) + (m1 - ws1 / l1) * 1.4426950408889634f;
    }
    size_t obase = ((size_t)(b * Sc + i0 + g)) * Dc + h * 64;
#pragma unroll
    for (int nt = 0; nt < 8; nt++) {
        float v0 = o[nt][0] * li0, v1 = o[nt][1] * li0;
        float v2 = o[nt][2] * li1, v3 = o[nt][3] * li1;
        size_t o0 = obase + nt * 8 + c2;
        size_t o1 = obase + 8 * Dc + nt * 8 + c2;
        *(u32*)(g_aoh + o0) = pkbf(v0, v1);
        *(u32*)(g_aol + o0) = pkbf(bflo(v0), bflo(v1));
        *(u32*)(g_aoh + o1) = pkbf(v2, v3);
        *(u32*)(g_aol + o1) = pkbf(bflo(v2), bflo(v3));
    }

    // ---- renorm epilogue: w = w' * exp(mu - m)/l -> canonical fp32 attn ----
    __syncthreads();               // K/V smem dead; reuse as staging
    float (*Ws)[68] = (float(*)[68])sm;   // 128 x 68 x 4 = 34816 B
    int ib0 = blockIdx.x * 128;
    int ro = w * 16 + g;
    for (int jt = 0; jt < 32; jt++) {
        int j0 = jt * 64;
        float ccA0 = __expf(muout[(jt * 2) * 16 + g * 2]         - m0) * li0;
        float ccA1 = __expf(muout[(jt * 2) * 16 + g * 2 + 1]     - m1) * li1;
        float ccB0 = __expf(muout[(jt * 2 + 1) * 16 + g * 2]     - m0) * li0;
        float ccB1 = __expf(muout[(jt * 2 + 1) * 16 + g * 2 + 1] - m1) * li1;
#pragma unroll
        for (int ff = 0; ff < 8; ff++) {
            float cc0 = (ff < 4) ? ccA0 : ccB0;
            float cc1 = (ff < 4) ? ccA1 : ccB1;
            uint2 pw = wout[(size_t)(jt * 8 + ff) * 32 + lane];
            float2 p01 = __half22float2(*(__half2*)&pw.x);
            float2 p23 = __half22float2(*(__half2*)&pw.y);
            Ws[ro][ff * 8 + c2]         = p01.x * cc0;
            Ws[ro][ff * 8 + c2 + 1]     = p01.y * cc0;
            Ws[ro + 8][ff * 8 + c2]     = p23.x * cc1;
            Ws[ro + 8][ff * 8 + c2 + 1] = p23.y * cc1;
        }
        __syncthreads();
#pragma unroll
        for (int r8 = 0; r8 < 8; r8++) {
            int id = t + r8 * 256;
            int row = id >> 4, c4 = (id & 15) * 4;
            *(float4*)(attnw + ((size_t)((b * Sc + ib0 + row) * Hc + h)) * Sc + j0 + c4) =
                *(float4*)&Ws[row][c4];
        }
        __syncthreads();
    }
}

extern "C" void kernel_launch(void* const* d_in, const int* in_sizes, int n_in,
                              void* d_out, int out_size) {
    (void)in_sizes; (void)n_in; (void)out_size;
    const float* x    = (const float*)d_in[0];
    const float* cosb = (const float*)d_in[1];
    const float* sinb = (const float*)d_in[2];

    float* out  = (float*)d_out;
    float* attn = out + (size_t)Mc * Dc;
    float* ent  = attn + (size_t)Mc * Hc * (size_t)Sc;

    bf16 *xh, *xl, *aoh, *aol;
    cudaGetSymbolAddress((void**)&xh, g_xh);   cudaGetSymbolAddress((void**)&xl, g_xl);
    cudaGetSymbolAddress((void**)&aoh, g_aoh); cudaGetSymbolAddress((void**)&aol, g_aol);

    cudaFuncSetAttribute(attn1, cudaFuncAttributeMaxDynamicSharedMemorySize, ATTN1_SMEM);

    cvt_all<<<8192, 256>>>(x, (const float*)d_in[3], (const float*)d_in[4],
                           (const float*)d_in[5], (const float*)d_in[6]);

    gemm_bf3<<<dim3(24, Mc / 128), 256>>>(xh, xl, nullptr, cosb, sinb, 1);
    vtrans<<<dim3(Sc / 32, Dc / 32, Bc), 256>>>();
    attn1<<<dim3(Sc / 128, Bc * Hc), 256, ATTN1_SMEM>>>(ent, attn);
    gemm_bf3<<<dim3(8, Mc / 128), 256>>>(aoh, aol, out, cosb, sinb, 0);
}

// round 17
// speedup vs baseline: 1.6408x; 1.6408x over previous
#include <cuda_runtime.h>
#include <cuda_bf16.h>
#include <cuda_fp16.h>

#define Bc 2
#define Sc 2048
#define Dc 1024
#define Hc 16
#define Mc (Bc*Sc)

typedef unsigned u32;
typedef __nv_bfloat16 bf16;

// ---------------- scratch ----------------
__device__ bf16 g_xh[(size_t)Mc*Dc], g_xl[(size_t)Mc*Dc];
__device__ bf16 g_wh[4*Dc*Dc], g_wl[4*Dc*Dc];
__device__ bf16 g_qh[(size_t)Mc*Dc], g_ql[(size_t)Mc*Dc];
__device__ bf16 g_kh[(size_t)Mc*Dc], g_kl[(size_t)Mc*Dc];
__device__ __half g_vth[(size_t)Bc*Dc*Sc];
__device__ bf16 g_aoh[(size_t)Mc*Dc], g_aol[(size_t)Mc*Dc];
__device__ float g_v[(size_t)Mc*Dc];
__device__ float g_m[Mc*Hc], g_l[Mc*Hc];
__device__ __half g_wraw[(size_t)Mc*Hc*Sc];   // w' fp16, frag-native
__device__ float g_mu[(size_t)4096*1024];      // per (wg, tile, sub, row) m_used

// ---------------- helpers ----------------
__device__ __forceinline__ void mma16816(float* c, const u32* a, const u32* b) {
    asm volatile("mma.sync.aligned.m16n8k16.row.col.f32.bf16.bf16.f32 "
        "{%0,%1,%2,%3},{%4,%5,%6,%7},{%8,%9},{%0,%1,%2,%3};"
        : "+f"(c[0]), "+f"(c[1]), "+f"(c[2]), "+f"(c[3])
        : "r"(a[0]), "r"(a[1]), "r"(a[2]), "r"(a[3]), "r"(b[0]), "r"(b[1]));
}
__device__ __forceinline__ void mma16816h(float* c, const u32* a, const u32* b) {
    asm volatile("mma.sync.aligned.m16n8k16.row.col.f32.f16.f16.f32 "
        "{%0,%1,%2,%3},{%4,%5,%6,%7},{%8,%9},{%0,%1,%2,%3};"
        : "+f"(c[0]), "+f"(c[1]), "+f"(c[2]), "+f"(c[3])
        : "r"(a[0]), "r"(a[1]), "r"(a[2]), "r"(a[3]), "r"(b[0]), "r"(b[1]));
}
__device__ __forceinline__ void ldsm4(u32* r, u32 a) {
    asm volatile("ldmatrix.sync.aligned.m8n8.x4.shared.b16 {%0,%1,%2,%3}, [%4];"
        : "=r"(r[0]), "=r"(r[1]), "=r"(r[2]), "=r"(r[3]) : "r"(a));
}
__device__ __forceinline__ u32 smem_u32(const void* p) {
    return (u32)__cvta_generic_to_shared(p);
}
__device__ __forceinline__ u32 pkbf(float x, float y) {
    bf16 a = __float2bfloat16(x), b = __float2bfloat16(y);
    return (u32)__bfloat16_as_ushort(a) | ((u32)__bfloat16_as_ushort(b) << 16);
}
__device__ __forceinline__ float bflo(float x) {
    return x - __bfloat162float(__float2bfloat16(x));
}
__device__ __forceinline__ void cpa16(void* s, const void* g) {
    u32 ss = (u32)__cvta_generic_to_shared(s);
    asm volatile("cp.async.ca.shared.global [%0], [%1], 16;" :: "r"(ss), "l"(g));
}
__device__ __forceinline__ void cpcommit() { asm volatile("cp.async.commit_group;"); }
template<int N> __device__ __forceinline__ void cpwait() { asm volatile("cp.async.wait_group %0;" :: "n"(N)); }

// FMA-pipe exp (x <= 0), rel err ~4e-5
__device__ __forceinline__ float fexp(float x) {
    float y = fmaf(x, 1.4426950408889634f, 12582912.0f);
    float n = y - 12582912.0f;
    float f = fmaf(x, 1.4426950408889634f, -n);
    float p = 0.00961812910f;
    p = fmaf(p, f, 0.05550410866f);
    p = fmaf(p, f, 0.24022650696f);
    p = fmaf(p, f, 0.69314718056f);
    p = fmaf(p, f, 1.0f);
    return __int_as_float(__float_as_int(p) + (__float_as_int(y) << 23));
}

// ---------------- merged conversions: x + 4 weights in one launch ----------------
__global__ __launch_bounds__(256) void cvt_all(const float* __restrict__ x,
                                               const float* __restrict__ w0,
                                               const float* __restrict__ w1,
                                               const float* __restrict__ w2,
                                               const float* __restrict__ w3) {
    int bi = blockIdx.x;
    const float* in;
    bf16 *oh, *ol;
    size_t i;
    if (bi < 4096) {
        in = x; oh = g_xh; ol = g_xl;
        i = (size_t)bi * 256 + threadIdx.x;
    } else {
        int wi = (bi - 4096) >> 10;
        in = wi == 0 ? w0 : wi == 1 ? w1 : wi == 2 ? w2 : w3;
        oh = g_wh + (size_t)wi * Dc * Dc;
        ol = g_wl + (size_t)wi * Dc * Dc;
        i = (size_t)((bi - 4096) & 1023) * 256 + threadIdx.x;
    }
    float4 v = ((const float4*)in)[i];
    ((uint2*)oh)[i] = make_uint2(pkbf(v.x, v.y), pkbf(v.z, v.w));
    ((uint2*)ol)[i] = make_uint2(pkbf(bflo(v.x), bflo(v.y)), pkbf(bflo(v.z), bflo(v.w)));
}

__global__ __launch_bounds__(256) void vtrans() {
    __shared__ float ts[32][33];
    int tx = threadIdx.x & 31, ty = threadIdx.x >> 5;
    int s0 = blockIdx.x * 32, d0 = blockIdx.y * 32, b = blockIdx.z;
#pragma unroll
    for (int i = 0; i < 4; i++)
        ts[ty + i * 8][tx] = g_v[((size_t)(b * Sc + s0 + ty + i * 8)) * Dc + d0 + tx];
    __syncthreads();
#pragma unroll
    for (int i = 0; i < 4; i++) {
        int d = ty + i * 8;
        size_t o = ((size_t)(b * Dc + d0 + d)) * Sc + s0 + tx;
        g_vth[o] = __float2half(ts[tx][d]);
    }
}

// ============ QKV merged / out-proj 3-term bf16 GEMM ============
__global__ __launch_bounds__(256, 2) void gemm_bf3(
    const bf16* __restrict__ Ah0, const bf16* __restrict__ Al0,
    float* __restrict__ Cf,
    const float* __restrict__ cosb, const float* __restrict__ sinb, int qkv) {
    __shared__ bf16 Ahs[2][128][24], Als[2][128][24], Bhs[2][128][24], Bls[2][128][24];
    int t = threadIdx.x, lane = t & 31, w = t >> 5;
    int wm = w & 1, wn = w >> 1;
    int g = lane >> 2, c2 = (lane & 3) * 2;
    int which = qkv ? (blockIdx.x >> 3) : 3;
    int bcol = (blockIdx.x & 7) * 128;
    int brow = blockIdx.y * 128;
    const bf16* Ah = Ah0;
    const bf16* Al = Al0;
    const bf16* Bh = g_wh + (size_t)which * Dc * Dc;
    const bf16* Bl = g_wl + (size_t)which * Dc * Dc;

    float acc[4][4][4];
#pragma unroll
    for (int a = 0; a < 4; a++)
#pragma unroll
        for (int b2 = 0; b2 < 4; b2++)
#pragma unroll
            for (int q = 0; q < 4; q++) acc[a][b2][q] = 0.f;

    int arow = wm * 64 + ((lane >> 3) & 1) * 8 + (lane & 7);
    int acol = ((lane >> 4) & 1) * 8;
    int brw  = wn * 32 + ((lane >> 4) & 1) * 8 + (lane & 7);
    int bcl  = ((lane >> 3) & 1) * 8;

    int lr = t >> 1, lc = (t & 1) * 8;
    const bf16* pah = Ah + (size_t)(brow + lr) * Dc + lc;
    const bf16* pal = Al + (size_t)(brow + lr) * Dc + lc;
    const bf16* pbh = Bh + (size_t)(bcol + lr) * Dc + lc;
    const bf16* pbl = Bl + (size_t)(bcol + lr) * Dc + lc;

#define GLOAD(st, k0) { \
        cpa16(&Ahs[st][lr][lc], pah + (k0)); cpa16(&Als[st][lr][lc], pal + (k0)); \
        cpa16(&Bhs[st][lr][lc], pbh + (k0)); cpa16(&Bls[st][lr][lc], pbl + (k0)); }

    GLOAD(0, 0); cpcommit();
    for (int kt = 0; kt < 64; kt++) {
        cpwait<0>();
        __syncthreads();
        if (kt < 63) { GLOAD((kt + 1) & 1, (kt + 1) * 16); cpcommit(); }
        int st = kt & 1;
        u32 aBH = smem_u32(&Ahs[st][arow][acol]);
        u32 aBL = smem_u32(&Als[st][arow][acol]);
        u32 bBH = smem_u32(&Bhs[st][brw][bcl]);
        u32 bBL = smem_u32(&Bls[st][brw][bcl]);
        u32 a_h[4][4], a_l[4][4], b_h[2][4], b_l[2][4];
#pragma unroll
        for (int mf = 0; mf < 4; mf++) {
            ldsm4(a_h[mf], aBH + mf * 768);
            ldsm4(a_l[mf], aBL + mf * 768);
        }
#pragma unroll
        for (int nfp = 0; nfp < 2; nfp++) {
            ldsm4(b_h[nfp], bBH + nfp * 768);
            ldsm4(b_l[nfp], bBL + nfp * 768);
        }
#pragma unroll
        for (int nf = 0; nf < 4; nf++) {
            const u32* bh2 = &b_h[nf >> 1][(nf & 1) * 2];
            const u32* bl2 = &b_l[nf >> 1][(nf & 1) * 2];
#pragma unroll
            for (int mf = 0; mf < 4; mf++) {
                mma16816(acc[mf][nf], a_h[mf], bh2);
                mma16816(acc[mf][nf], a_h[mf], bl2);
                mma16816(acc[mf][nf], a_l[mf], bh2);
            }
        }
    }
#undef GLOAD
    if (which >= 2) {
        float* dst = (which == 2) ? g_v : Cf;
#pragma unroll
        for (int mf = 0; mf < 4; mf++)
#pragma unroll
            for (int nf = 0; nf < 4; nf++) {
                int r = brow + wm * 64 + mf * 16 + g;
                int c = bcol + wn * 32 + nf * 8 + c2;
                *(float2*)&dst[(size_t)r * Dc + c]       = make_float2(acc[mf][nf][0], acc[mf][nf][1]);
                *(float2*)&dst[(size_t)(r + 8) * Dc + c] = make_float2(acc[mf][nf][2], acc[mf][nf][3]);
            }
    } else {
        bf16* Ch = which == 0 ? g_qh : g_kh;
        bf16* Cl = which == 0 ? g_ql : g_kl;
#pragma unroll
        for (int mf = 0; mf < 4; mf++)
#pragma unroll
            for (int nf = 0; nf < 4; nf++) {
                int r = brow + wm * 64 + mf * 16 + g;
                int c = bcol + wn * 32 + nf * 8 + c2;
                int pi = (c & 63) >> 1;
                int sA = r & 2047, sB = (r + 8) & 2047;
                float csA = cosb[sA * 32 + pi], snA = sinb[sA * 32 + pi];
                float csB = cosb[sB * 32 + pi], snB = sinb[sB * 32 + pi];
                float a0 = acc[mf][nf][0], a1 = acc[mf][nf][1];
                float a2 = acc[mf][nf][2], a3 = acc[mf][nf][3];
                float o0 = a0 * csA - a1 * snA, o1 = a0 * snA + a1 * csA;
                float o2 = a2 * csB - a3 * snB, o3 = a2 * snB + a3 * csB;
                size_t off = (size_t)r * Dc + c;
                *(u32*)(Ch + off) = pkbf(o0, o1);
                *(u32*)(Cl + off) = pkbf(bflo(o0), bflo(o1));
                off = (size_t)(r + 8) * Dc + c;
                *(u32*)(Ch + off) = pkbf(o2, o3);
                *(u32*)(Cl + off) = pkbf(bflo(o2), bflo(o3));
            }
    }
}

// ---------------- fused pass 1 (flash), 1-term fp16 AV ----------------
#define ATTN1_SMEM 55296
__global__ __launch_bounds__(256, 2) void attn1(float* __restrict__ ent) {
    extern __shared__ char sm[];
    bf16*   KH = (bf16*)sm;
    bf16*   KL = (bf16*)(sm + 18432);
    __half* VH = (__half*)(sm + 36864);
#define KHS(st,r,c) (KH + (st)*4608 + (r)*72 + (c))
#define KLS(st,r,c) (KL + (st)*4608 + (r)*72 + (c))
#define VHS(st,r,c) (VH + (st)*4608 + (r)*72 + (c))
    int t = threadIdx.x, lane = t & 31, w = t >> 5;
    int g = lane >> 2, c2 = (lane & 3) * 2;
    int b = blockIdx.y >> 4, h = blockIdx.y & 15;
    int i0 = blockIdx.x * 128 + w * 16;

    const bf16* qh = g_qh + ((size_t)(b * Sc + i0 + g)) * Dc + h * 64;
    const bf16* ql = g_ql + ((size_t)(b * Sc + i0 + g)) * Dc + h * 64;
    u32 ah[4][4], al[4][4];
#pragma unroll
    for (int kf = 0; kf < 4; kf++) {
        ah[kf][0] = *(const u32*)(qh + kf * 16 + c2);
        ah[kf][1] = *(const u32*)(qh + 8 * Dc + kf * 16 + c2);
        ah[kf][2] = *(const u32*)(qh + kf * 16 + c2 + 8);
        ah[kf][3] = *(const u32*)(qh + 8 * Dc + kf * 16 + c2 + 8);
        al[kf][0] = *(const u32*)(ql + kf * 16 + c2);
        al[kf][1] = *(const u32*)(ql + 8 * Dc + kf * 16 + c2);
        al[kf][2] = *(const u32*)(ql + kf * 16 + c2 + 8);
        al[kf][3] = *(const u32*)(ql + 8 * Dc + kf * 16 + c2 + 8);
    }

    int kr = t >> 2, kc = (t & 3) * 16;
    const bf16* kgh = g_kh + ((size_t)(b * Sc + kr)) * Dc + h * 64 + kc;
    const bf16* kgl = g_kl + ((size_t)(b * Sc + kr)) * Dc + h * 64 + kc;
    const __half* vgh = g_vth + ((size_t)(b * Dc + h * 64 + kr)) * Sc + kc;

#define TLOAD(st, j0) { \
        cpa16(KHS(st,kr,kc),     kgh + (size_t)(j0) * Dc); \
        cpa16(KHS(st,kr,kc+8),   kgh + (size_t)(j0) * Dc + 8); \
        cpa16(KLS(st,kr,kc),     kgl + (size_t)(j0) * Dc); \
        cpa16(KLS(st,kr,kc+8),   kgl + (size_t)(j0) * Dc + 8); \
        cpa16(VHS(st,kr,kc),     vgh + (j0)); \
        cpa16(VHS(st,kr,kc+8),   vgh + (j0) + 8); }

    int brow = ((lane >> 4) & 1) * 8 + (lane & 7);
    int bcol = ((lane >> 3) & 1) * 8;

    float m0 = -1e30f, m1 = -1e30f, l0 = 0.f, l1 = 0.f, ws0 = 0.f, ws1 = 0.f;
    float o[8][4];
#pragma unroll
    for (int n = 0; n < 8; n++)
#pragma unroll
        for (int q = 0; q < 4; q++) o[n][q] = 0.f;

    size_t wg = ((size_t)blockIdx.y * 16 + blockIdx.x) * 8 + w;
    uint2* wout = (uint2*)g_wraw + wg * 8192;
    float* muout = g_mu + wg * 1024;

    TLOAD(0, 0); cpcommit();
    for (int jt = 0; jt < 32; jt++) {
        int j0 = jt * 64;
        cpwait<0>();
        __syncthreads();
        if (jt < 31) { TLOAD((jt + 1) & 1, j0 + 64); cpcommit(); }
        int st = jt & 1;
        u32 kBH0 = smem_u32(KHS(st, brow, bcol));
        u32 kBL0 = smem_u32(KLS(st, brow, bcol));
        u32 vBH = smem_u32(VHS(st, brow, bcol));
#pragma unroll
        for (int sub = 0; sub < 2; sub++) {
            u32 kBH = kBH0 + sub * 32 * 144;
            u32 kBL = kBL0 + sub * 32 * 144;
            float sc[4][4];
#pragma unroll
            for (int nt = 0; nt < 4; nt++) { sc[nt][0] = sc[nt][1] = sc[nt][2] = sc[nt][3] = 0.f; }
#pragma unroll
            for (int ntp = 0; ntp < 2; ntp++) {
#pragma unroll
                for (int kf = 0; kf < 4; kf++) {
                    u32 off = (u32)(ntp * 16 * 144 + kf * 32);
                    u32 bh4[4], bl4[4];
                    ldsm4(bh4, kBH + off);
                    ldsm4(bl4, kBL + off);
                    mma16816(sc[2 * ntp],     ah[kf], &bh4[0]);
                    mma16816(sc[2 * ntp],     ah[kf], &bl4[0]);
                    mma16816(sc[2 * ntp],     al[kf], &bh4[0]);
                    mma16816(sc[2 * ntp + 1], ah[kf], &bh4[2]);
                    mma16816(sc[2 * ntp + 1], ah[kf], &bl4[2]);
                    mma16816(sc[2 * ntp + 1], al[kf], &bh4[2]);
                }
            }
#pragma unroll
            for (int nt = 0; nt < 4; nt++) {
                sc[nt][0] *= 0.125f; sc[nt][1] *= 0.125f; sc[nt][2] *= 0.125f; sc[nt][3] *= 0.125f;
            }
            float tm0 = -1e30f, tm1 = -1e30f;
#pragma unroll
            for (int nt = 0; nt < 4; nt++) {
                tm0 = fmaxf(tm0, fmaxf(sc[nt][0], sc[nt][1]));
                tm1 = fmaxf(tm1, fmaxf(sc[nt][2], sc[nt][3]));
            }
            tm0 = fmaxf(tm0, __shfl_xor_sync(~0u, tm0, 1));
            tm0 = fmaxf(tm0, __shfl_xor_sync(~0u, tm0, 2));
            tm1 = fmaxf(tm1, __shfl_xor_sync(~0u, tm1, 1));
            tm1 = fmaxf(tm1, __shfl_xor_sync(~0u, tm1, 2));
            float mn0 = fmaxf(m0, tm0), mn1 = fmaxf(m1, tm1);
            float cr0 = __expf(m0 - mn0), cr1 = __expf(m1 - mn1);
            l0 *= cr0; ws0 *= cr0; l1 *= cr1; ws1 *= cr1;
#pragma unroll
            for (int nt = 0; nt < 4; nt++) {
                float e0 = fexp(sc[nt][0] - mn0), e1 = fexp(sc[nt][1] - mn0);     // FMA pipe
                float e2 = __expf(sc[nt][2] - mn1), e3 = __expf(sc[nt][3] - mn1); // MUFU pipe
                l0 += e0 + e1;
                ws0 = fmaf(e0, sc[nt][0], fmaf(e1, sc[nt][1], ws0));
                l1 += e2 + e3;
                ws1 = fmaf(e2, sc[nt][2], fmaf(e3, sc[nt][3], ws1));
                __half2 p01 = __floats2half2_rn(e0, e1);
                __half2 p23 = __floats2half2_rn(e2, e3);
                u32 u01 = *(u32*)&p01, u23 = *(u32*)&p23;
                wout[(size_t)(j0 / 8 + sub * 4 + nt) * 32 + lane] = make_uint2(u01, u23);
                sc[nt][0] = __uint_as_float(u01);
                sc[nt][1] = __uint_as_float(u23);
            }
            m0 = mn0; m1 = mn1;
            if ((lane & 3) == 0) {
                muout[(jt * 2 + sub) * 16 + g * 2]     = mn0;
                muout[(jt * 2 + sub) * 16 + g * 2 + 1] = mn1;
            }
#pragma unroll
            for (int nt = 0; nt < 8; nt++) {
                o[nt][0] *= cr0; o[nt][1] *= cr0; o[nt][2] *= cr1; o[nt][3] *= cr1;
            }
#pragma unroll
            for (int ntp = 0; ntp < 4; ntp++) {
#pragma unroll
                for (int kf = 0; kf < 2; kf++) {
                    u32 off = (u32)(ntp * 16 * 144 + (sub * 2 + kf) * 32);
                    u32 vh4[4];
                    ldsm4(vh4, vBH + off);
                    u32 ahg[4] = { __float_as_uint(sc[2 * kf][0]), __float_as_uint(sc[2 * kf][1]),
                                   __float_as_uint(sc[2 * kf + 1][0]), __float_as_uint(sc[2 * kf + 1][1]) };
                    mma16816h(o[2 * ntp],     ahg, &vh4[0]);
                    mma16816h(o[2 * ntp + 1], ahg, &vh4[2]);
                }
            }
        }
    }
#undef TLOAD
#pragma unroll
    for (int x = 1; x < 4; x <<= 1) {
        float om = __shfl_xor_sync(~0u, m0, x), ol = __shfl_xor_sync(~0u, l0, x),
              ow = __shfl_xor_sync(~0u, ws0, x);
        float mn = fmaxf(m0, om), ca = __expf(m0 - mn), cb = __expf(om - mn);
        l0 = l0 * ca + ol * cb; ws0 = ws0 * ca + ow * cb; m0 = mn;
        om = __shfl_xor_sync(~0u, m1, x); ol = __shfl_xor_sync(~0u, l1, x);
        ow = __shfl_xor_sync(~0u, ws1, x);
        mn = fmaxf(m1, om); ca = __expf(m1 - mn); cb = __expf(om - mn);
        l1 = l1 * ca + ol * cb; ws1 = ws1 * ca + ow * cb; m1 = mn;
    }
    float li0 = 1.f / l0, li1 = 1.f / l1;
    if ((lane & 3) == 0) {
        int idx0 = (b * Sc + i0 + g) * Hc + h;
        g_m[idx0] = m0; g_l[idx0] = l0;
        g_m[idx0 + 8 * Hc] = m1; g_l[idx0 + 8 * Hc] = l1;
        ent[idx0]          = __log2f(l0) + (m0 - ws0 / l0) * 1.4426950408889634f;
        ent[idx0 + 8 * Hc] = __log2f(l1) + (m1 - ws1 / l1) * 1.4426950408889634f;
    }
    size_t obase = ((size_t)(b * Sc + i0 + g)) * Dc + h * 64;
#pragma unroll
    for (int nt = 0; nt < 8; nt++) {
        float v0 = o[nt][0] * li0, v1 = o[nt][1] * li0;
        float v2 = o[nt][2] * li1, v3 = o[nt][3] * li1;
        size_t o0 = obase + nt * 8 + c2;
        size_t o1 = obase + 8 * Dc + nt * 8 + c2;
        *(u32*)(g_aoh + o0) = pkbf(v0, v1);
        *(u32*)(g_aol + o0) = pkbf(bflo(v0), bflo(v1));
        *(u32*)(g_aoh + o1) = pkbf(v2, v3);
        *(u32*)(g_aol + o1) = pkbf(bflo(v2), bflo(v3));
    }
}

// ---------------- pass 2: pure renormalize + canonical write ----------------
__global__ __launch_bounds__(128) void attn_norm(float* __restrict__ attnw) {
    __shared__ float Ws[64][68];
    int t = threadIdx.x, lane = t & 31, w = t >> 5;
    int g = lane >> 2, c2 = (lane & 3) * 2;
    int b = blockIdx.y >> 4, h = blockIdx.y & 15;
    int ib = blockIdx.x;
    int i0 = ib * 64;
    int iw = i0 + w * 16;
    size_t wg = ((size_t)blockIdx.y * 16 + (ib >> 1)) * 8 + (ib & 1) * 4 + w;
    const uint2* win = (const uint2*)g_wraw + wg * 8192;
    const float* muin = g_mu + wg * 1024;
    int idx0 = (b * Sc + iw + g) * Hc + h;
    float m0 = g_m[idx0], li0 = 1.f / g_l[idx0];
    float m1 = g_m[idx0 + 8 * Hc], li1 = 1.f / g_l[idx0 + 8 * Hc];

    for (int jt = 0; jt < 32; jt++) {
        int j0 = jt * 64;
        float ccA0 = __expf(muin[(jt * 2) * 16 + g * 2]         - m0) * li0;
        float ccA1 = __expf(muin[(jt * 2) * 16 + g * 2 + 1]     - m1) * li1;
        float ccB0 = __expf(muin[(jt * 2 + 1) * 16 + g * 2]     - m0) * li0;
        float ccB1 = __expf(muin[(jt * 2 + 1) * 16 + g * 2 + 1] - m1) * li1;
#pragma unroll
        for (int ff = 0; ff < 8; ff++) {
            float cc0 = (ff < 4) ? ccA0 : ccB0;
            float cc1 = (ff < 4) ? ccA1 : ccB1;
            uint2 pw = win[(size_t)(j0 / 8 + ff) * 32 + lane];
            float2 p01 = __half22float2(*(__half2*)&pw.x);
            float2 p23 = __half22float2(*(__half2*)&pw.y);
            int ro = w * 16 + g;
            Ws[ro][ff * 8 + c2]         = p01.x * cc0;
            Ws[ro][ff * 8 + c2 + 1]     = p01.y * cc0;
            Ws[ro + 8][ff * 8 + c2]     = p23.x * cc1;
            Ws[ro + 8][ff * 8 + c2 + 1] = p23.y * cc1;
        }
        __syncthreads();
#pragma unroll
        for (int r8 = 0; r8 < 8; r8++) {
            int id = t + r8 * 128;
            int row = id >> 4, c4 = (id & 15) * 4;
            *(float4*)(attnw + ((size_t)((b * Sc + i0 + row) * Hc + h)) * Sc + j0 + c4) =
                *(float4*)&Ws[row][c4];
        }
        __syncthreads();
    }
}

extern "C" void kernel_launch(void* const* d_in, const int* in_sizes, int n_in,
                              void* d_out, int out_size) {
    (void)in_sizes; (void)n_in; (void)out_size;
    const float* x    = (const float*)d_in[0];
    const float* cosb = (const float*)d_in[1];
    const float* sinb = (const float*)d_in[2];

    float* out  = (float*)d_out;
    float* attn = out + (size_t)Mc * Dc;
    float* ent  = attn + (size_t)Mc * Hc * (size_t)Sc;

    bf16 *xh, *xl, *aoh, *aol;
    cudaGetSymbolAddress((void**)&xh, g_xh);   cudaGetSymbolAddress((void**)&xl, g_xl);
    cudaGetSymbolAddress((void**)&aoh, g_aoh); cudaGetSymbolAddress((void**)&aol, g_aol);

    cudaFuncSetAttribute(attn1, cudaFuncAttributeMaxDynamicSharedMemorySize, ATTN1_SMEM);

    cvt_all<<<8192, 256>>>(x, (const float*)d_in[3], (const float*)d_in[4],
                           (const float*)d_in[5], (const float*)d_in[6]);

    gemm_bf3<<<dim3(24, Mc / 128), 256>>>(xh, xl, nullptr, cosb, sinb, 1);
    vtrans<<<dim3(Sc / 32, Dc / 32, Bc), 256>>>();
    attn1<<<dim3(Sc / 128, Bc * Hc), 256, ATTN1_SMEM>>>(ent);
    attn_norm<<<dim3(Sc / 64, Bc * Hc), 128>>>(attn);
    gemm_bf3<<<dim3(8, Mc / 128), 256>>>(aoh, aol, out, cosb, sinb, 0);
}